// round 1
// baseline (speedup 1.0000x reference)
#include <cuda_runtime.h>

// KPN 5x5 per-pixel convolution.
// frames: (B=16, N=1, C=3, H=256, W=256) float32
// core:   (B=16, N=1, 25,  C=3, H=256, W=256) float32
// out:    (B=16, C=3, H=256, W=256) float32   (N squeezed)
//
// pred[b,c,h,w] = sum_{i,j in 0..4} core[b,0,i*5+j,c,h,w] * frame_pad[b,0,c,h+i,w+j]
// with zero padding of 2 on each spatial side (rate=1).

#define KK 5
#define PAD 2
#define WID 256
#define HEI 256
#define CH 3
#define BATCH 16
#define TILE_H 4
#define SW (WID + 2 * PAD)   // 260

__global__ __launch_bounds__(WID * TILE_H, 2)
void kpn_conv_kernel(const float* __restrict__ frames,
                     const float* __restrict__ core,
                     float* __restrict__ out) {
    // blockIdx.x: row-tile index (H / TILE_H), blockIdx.y: channel, blockIdx.z: batch
    const int tile = blockIdx.x;
    const int c    = blockIdx.y;
    const int b    = blockIdx.z;
    const int h0   = tile * TILE_H;

    const size_t plane = (size_t)HEI * WID;                 // 65536
    const float* fbase = frames + ((size_t)b * CH + c) * plane;
    // core index: (((b*25 + idx)*C) + c) * H*W
    const float* cbase = core + ((size_t)b * 25 * CH + c) * plane;
    const size_t cstride = (size_t)CH * plane;              // stride between taps

    __shared__ float tile_s[TILE_H + 2 * PAD][SW];          // 8 x 260 floats = 8320 B

    // ---- Stage frame tile (zero-padded) into shared memory ----
    const int tid = threadIdx.y * WID + threadIdx.x;        // 0..1023
    const int nthreads = WID * TILE_H;                      // 1024
    const int total = (TILE_H + 2 * PAD) * SW;              // 2080
    for (int k = tid; k < total; k += nthreads) {
        const int r  = k / SW;
        const int cc = k - r * SW;
        const int gh = h0 - PAD + r;
        const int gw = cc - PAD;
        float v = 0.0f;
        if (gh >= 0 && gh < HEI && gw >= 0 && gw < WID)
            v = fbase[(size_t)gh * WID + gw];
        tile_s[r][cc] = v;
    }
    __syncthreads();

    // ---- Compute one output pixel per thread ----
    const int w  = threadIdx.x;
    const int ty = threadIdx.y;
    const int h  = h0 + ty;

    const float* crow = cbase + (size_t)h * WID + w;

    float acc = 0.0f;
#pragma unroll
    for (int i = 0; i < KK; i++) {
#pragma unroll
        for (int j = 0; j < KK; j++) {
            const int idx = i * KK + j;
            const float cv = __ldg(crow + (size_t)idx * cstride);
            acc = fmaf(cv, tile_s[ty + i][w + j], acc);
        }
    }

    out[((size_t)b * CH + c) * plane + (size_t)h * WID + w] = acc;
}

extern "C" void kernel_launch(void* const* d_in, const int* in_sizes, int n_in,
                              void* d_out, int out_size) {
    const float* frames = (const float*)d_in[0];
    const float* core   = (const float*)d_in[1];
    // d_in[2] = rate (int scalar) — fixed at 1 for this problem instance.
    float* out = (float*)d_out;

    dim3 block(WID, TILE_H, 1);                 // 1024 threads
    dim3 grid(HEI / TILE_H, CH, BATCH);         // 64 x 3 x 16 = 3072 CTAs
    kpn_conv_kernel<<<grid, block>>>(frames, core, out);
}

// round 2
// speedup vs baseline: 1.0043x; 1.0043x over previous
#include <cuda_runtime.h>

// KPN 5x5 per-pixel convolution, float4-vectorized.
// frames: (B=16, N=1, C=3, H=256, W=256) float32
// core:   (B=16, N=1, 25,  C=3, H=256, W=256) float32
// out:    (B=16, C=3, H=256, W=256) float32
//
// pred[b,c,h,w] = sum_{i,j} core[b,0,i*5+j,c,h,w] * frame_pad[b,0,c,h+i,w+j]
// zero padding 2 on each spatial side (rate=1).

#define KK 5
#define PAD 2
#define WID 256
#define HEI 256
#define CH 3
#define TILE_H 4
#define TX 64                       // threads in x; each covers 4 pixels
#define SW (WID + 2 * PAD)          // 260 (260*4B = 1040B row stride, 16B-aligned)

__global__ __launch_bounds__(TX * TILE_H, 4)
void kpn_conv_kernel(const float* __restrict__ frames,
                     const float* __restrict__ core,
                     float* __restrict__ out) {
    const int tile = blockIdx.x;    // H / TILE_H
    const int c    = blockIdx.y;    // channel
    const int b    = blockIdx.z;    // batch
    const int h0   = tile * TILE_H;

    const size_t plane   = (size_t)HEI * WID;                 // 65536
    const float* fbase   = frames + ((size_t)b * CH + c) * plane;
    const float* cbase   = core   + ((size_t)b * 25 * CH + c) * plane;
    const size_t cstride = (size_t)CH * plane;                // stride between taps

    __shared__ __align__(16) float tile_s[TILE_H + 2 * PAD][SW]; // 8 x 260 = 8320 B

    // ---- Stage zero-padded frame tile into shared memory ----
    const int tid      = threadIdx.y * TX + threadIdx.x;      // 0..255
    const int nthreads = TX * TILE_H;                         // 256
    const int total    = (TILE_H + 2 * PAD) * SW;             // 2080
    for (int k = tid; k < total; k += nthreads) {
        const int r  = k / SW;
        const int cc = k - r * SW;
        const int gh = h0 - PAD + r;
        const int gw = cc - PAD;
        float v = 0.0f;
        if (gh >= 0 && gh < HEI && gw >= 0 && gw < WID)
            v = fbase[(size_t)gh * WID + gw];
        tile_s[r][cc] = v;
    }
    __syncthreads();

    // ---- Each thread computes 4 consecutive output pixels ----
    const int w4 = threadIdx.x * 4;       // first pixel column
    const int ty = threadIdx.y;
    const int h  = h0 + ty;

    const float* crow = cbase + (size_t)h * WID + w4;

    float4 acc = make_float4(0.f, 0.f, 0.f, 0.f);

#pragma unroll
    for (int i = 0; i < KK; i++) {
        // 8-float smem window covers cols w4..w4+7 (pixels p=0..3, taps j=0..4)
        const float4 s0 = *reinterpret_cast<const float4*>(&tile_s[ty + i][w4]);
        const float4 s1 = *reinterpret_cast<const float4*>(&tile_s[ty + i][w4 + 4]);
        const float s[8] = {s0.x, s0.y, s0.z, s0.w, s1.x, s1.y, s1.z, s1.w};

#pragma unroll
        for (int j = 0; j < KK; j++) {
            const int idx = i * KK + j;
            const float4 cv =
                *reinterpret_cast<const float4*>(crow + (size_t)idx * cstride);
            acc.x = fmaf(cv.x, s[j + 0], acc.x);
            acc.y = fmaf(cv.y, s[j + 1], acc.y);
            acc.z = fmaf(cv.z, s[j + 2], acc.z);
            acc.w = fmaf(cv.w, s[j + 3], acc.w);
        }
    }

    float* orow = out + ((size_t)b * CH + c) * plane + (size_t)h * WID + w4;
    *reinterpret_cast<float4*>(orow) = acc;
}

extern "C" void kernel_launch(void* const* d_in, const int* in_sizes, int n_in,
                              void* d_out, int out_size) {
    const float* frames = (const float*)d_in[0];
    const float* core   = (const float*)d_in[1];
    // d_in[2] = rate (scalar, fixed 1 for this instance)
    float* out = (float*)d_out;

    dim3 block(TX, TILE_H, 1);              // 256 threads
    dim3 grid(HEI / TILE_H, CH, 16);        // 64 x 3 x 16 = 3072 CTAs
    kpn_conv_kernel<<<grid, block>>>(frames, core, out);
}

// round 3
// speedup vs baseline: 1.1132x; 1.1084x over previous
#include <cuda_runtime.h>

// KPN 5x5 per-pixel convolution, float4-vectorized, spread-aware.
// frames: (B=16, N=1, C=3, H=256, W=256) float32
// core:   (B=16, N=1, 25,  C=3, H=256, W=256) float32
// out:    (B=16, C=3, H=256, W=256) float32
//
// pred[b,c,h,w] = sum_{i,j} core[b,0,i*5+j,c,h,w] * frame_pad[b,0,c,h+i,w+j]
// zero padding 2 each spatial side (rate=1).

#define KK 5
#define PAD 2
#define WID 256
#define HEI 256
#define CH 3
#define TILE_H 4
#define TX 64                       // threads in x; each covers 4 pixels
#define SW (WID + 2 * PAD)          // 260 floats per smem row (1040B, 16B-aligned)

__global__ __launch_bounds__(TX * TILE_H, 6)
void kpn_conv_kernel(const float* __restrict__ frames,
                     const float* __restrict__ core,
                     float* __restrict__ out) {
    const int tile = blockIdx.x;    // H / TILE_H
    const int c    = blockIdx.y;    // channel
    const int b    = blockIdx.z;    // batch
    const int h0   = tile * TILE_H;

    const size_t plane   = (size_t)HEI * WID;                 // 65536
    const float* fbase   = frames + ((size_t)b * CH + c) * plane;
    const float* cbase   = core   + ((size_t)b * 25 * CH + c) * plane;
    const size_t cstride = (size_t)CH * plane;                // tap stride

    __shared__ __align__(16) float tile_s[TILE_H + 2 * PAD][SW]; // 8 x 260 = 8320 B

    // ---- Stage zero-padded frame tile into shared memory ----
    const int tid      = threadIdx.y * TX + threadIdx.x;      // 0..255
    const int nthreads = TX * TILE_H;                         // 256
    const int total    = (TILE_H + 2 * PAD) * SW;             // 2080
    for (int k = tid; k < total; k += nthreads) {
        const int r  = k / SW;
        const int cc = k - r * SW;
        const int gh = h0 - PAD + r;
        const int gw = cc - PAD;
        float v = 0.0f;
        if (gh >= 0 && gh < HEI && gw >= 0 && gw < WID)
            v = fbase[(size_t)gh * WID + gw];
        tile_s[r][cc] = v;
    }
    __syncthreads();

    // ---- Each thread computes 4 consecutive output pixels ----
    const int w4 = threadIdx.x * 4;
    const int ty = threadIdx.y;
    const int h  = h0 + ty;

    const float* crow = cbase + (size_t)h * WID + w4;

    float4 acc = make_float4(0.f, 0.f, 0.f, 0.f);

    // i-loop deliberately NOT unrolled: keeps the front-batched LDG run
    // (MLP_p1) at ~5 instead of 25, avoiding the cross-CTA L1tex-queue
    // contention / 2x CTA-spread regime.
#pragma unroll 1
    for (int i = 0; i < KK; i++) {
        const float4 s0 = *reinterpret_cast<const float4*>(&tile_s[ty + i][w4]);
        const float4 s1 = *reinterpret_cast<const float4*>(&tile_s[ty + i][w4 + 4]);
        const float s[8] = {s0.x, s0.y, s0.z, s0.w, s1.x, s1.y, s1.z, s1.w};

        const float* ci = crow + (size_t)(i * KK) * cstride;
#pragma unroll
        for (int j = 0; j < KK; j++) {
            // streaming load: core is read exactly once — evict-first
            const float4 cv =
                __ldcs(reinterpret_cast<const float4*>(ci + (size_t)j * cstride));
            acc.x = fmaf(cv.x, s[j + 0], acc.x);
            acc.y = fmaf(cv.y, s[j + 1], acc.y);
            acc.z = fmaf(cv.z, s[j + 2], acc.z);
            acc.w = fmaf(cv.w, s[j + 3], acc.w);
        }
    }

    float* orow = out + ((size_t)b * CH + c) * plane + (size_t)h * WID + w4;
    __stcs(reinterpret_cast<float4*>(orow), acc);
}

extern "C" void kernel_launch(void* const* d_in, const int* in_sizes, int n_in,
                              void* d_out, int out_size) {
    const float* frames = (const float*)d_in[0];
    const float* core   = (const float*)d_in[1];
    // d_in[2] = rate (scalar, fixed 1 for this instance)
    float* out = (float*)d_out;

    dim3 block(TX, TILE_H, 1);              // 256 threads
    dim3 grid(HEI / TILE_H, CH, 16);        // 64 x 3 x 16 = 3072 CTAs
    kpn_conv_kernel<<<grid, block>>>(frames, core, out);
}